// round 2
// baseline (speedup 1.0000x reference)
#include <cuda_runtime.h>

// AdaptiveSample, smem-staged version:
//   weights: softmax over 15 sampled taps of valid*posw*guide (per pixel)
//   out[b,c,h,w] = sum_s wv[s] * feat[b,c,h+dy_s,w+dx_s]  (zero-pad via masked weights)
//   second output = passthrough copy of features.

namespace {
constexpr int H  = 256;
constexpr int W  = 512;
constexpr int C  = 32;
constexpr int S  = 15;
constexpr int KS = 5;
constexpr int KK = 25;
constexpr int HW = H * W;

constexpr int BW = 32;           // tile width  (warp-coalesced)
constexpr int BH = 8;            // tile height
constexpr int NT = BW * BH;      // 256 threads

constexpr int FP   = 40;         // feature smem pitch (floats): cols w0-4 .. w0+35
constexpr int FR   = 12;         // feature smem rows:           h0-2 .. h0+9
constexpr int SLOT = FP * FR;    // 480 floats per channel
constexpr int NC   = 4;          // channels staged per group
constexpr int NG   = C / NC;     // 8 groups
constexpr int GBUF = BH * BW * KK;  // guide tile floats (6400)
}

__global__ __launch_bounds__(NT, 5)
void adaptive_sample_kernel(const float* __restrict__ depth,
                            const float* __restrict__ features,
                            const float* __restrict__ guide,
                            const int*   __restrict__ sidx,
                            float* __restrict__ out,
                            float* __restrict__ outf,
                            int do_copy)
{
    // Guide tile first, then reused as double-buffered feature tiles (2*NC*SLOT = 3840 <= 6400).
    __shared__ float       shg[GBUF];
    __shared__ float       sh_posw[S];
    __shared__ int         sh_k[S];
    __shared__ signed char sh_dy[S], sh_dx[S];

    const int tx  = threadIdx.x;
    const int ty  = threadIdx.y;
    const int tid = ty * BW + tx;
    const int w0  = blockIdx.x * BW;
    const int h0  = blockIdx.y * BH;
    const int b   = blockIdx.z;

    // ---- tap metadata (one thread; S=15 trivial) ----
    if (tid == 0) {
        float pw[S];
        float sum = 0.f;
        #pragma unroll
        for (int s = 0; s < S; ++s) {
            int k  = sidx[s];
            int px = k % KS;
            int py = k / KS;
            float fx = (float)px - 2.f;
            float fy = (float)py - 2.f;
            float v  = __expf(-0.5f * sqrtf(fx * fx + fy * fy));
            pw[s] = v; sum += v;
            sh_k[s]  = k;
            sh_dy[s] = (signed char)(py - 2);
            sh_dx[s] = (signed char)(px - 2);
        }
        float inv = 1.f / sum;
        #pragma unroll
        for (int s = 0; s < S; ++s) sh_posw[s] = pw[s] * inv;
    }

    // ---- stage guide tile (contiguous float4 rows; 800 floats per image row) ----
    {
        #pragma unroll
        for (int it = 0; it < (GBUF / 4 + NT - 1) / NT; ++it) {
            int i4 = tid + it * NT;
            if (i4 < GBUF / 4) {
                int row = i4 / (BW * KK / 4);
                int in4 = i4 - row * (BW * KK / 4);
                const float4* src = reinterpret_cast<const float4*>(
                    guide + (((size_t)b * H + (h0 + row)) * W + w0) * KK) + in4;
                reinterpret_cast<float4*>(shg + row * BW * KK)[in4] = *src;
            }
        }
    }
    __syncthreads();

    const int h = h0 + ty;
    const int w = w0 + tx;

    // ---- per-pixel softmax weights + smem tap offsets ----
    const float* drow = depth + (size_t)b * HW;
    const float* gpix = shg + (ty * BW + tx) * KK;   // lane stride 25: conflict-free

    float wv[S];
    int   toff[S];
    unsigned ibm  = 0u;
    float    gmax = 0.f;  // logits >= 0
    #pragma unroll
    for (int s = 0; s < S; ++s) {
        int dy = (int)sh_dy[s], dx = (int)sh_dx[s];
        int hh = h + dy, ww = w + dx;
        bool ib = ((unsigned)hh < (unsigned)H) && ((unsigned)ww < (unsigned)W);
        float d = ib ? __ldg(drow + hh * W + ww) : 0.f;
        bool valid = ib && (d > 0.f) && (d < 192.0f);
        float logit = valid ? sh_posw[s] * gpix[sh_k[s]] : 0.f;
        wv[s] = logit;
        gmax  = fmaxf(gmax, logit);
        ibm  |= (unsigned)ib << s;
        toff[s] = (ty + 2 + dy) * FP + (tx + 4 + dx);
    }
    float esum = 0.f;
    #pragma unroll
    for (int s = 0; s < S; ++s) { wv[s] = __expf(wv[s] - gmax); esum += wv[s]; }
    float inv = 1.f / esum;
    #pragma unroll
    for (int s = 0; s < S; ++s)
        wv[s] = ((ibm >> s) & 1u) ? wv[s] * inv : 0.f;  // OOB tap == zero-padded feature

    __syncthreads();  // guide reads done; shg becomes feature buffers

    // ---- channel groups: double-buffered smem staging + tap FMAs ----
    const float* fbase = features + (size_t)b * C * HW;
    const size_t pix   = (size_t)h * W + w;
    float* obase  = out  + (size_t)b * C * HW + pix;
    float* ocbase = outf + (size_t)b * C * HW;

    auto stage = [&](int g, int buf) {
        #pragma unroll
        for (int j = 0; j < NC; ++j) {
            const float* fc  = fbase + (size_t)(g * NC + j) * HW;
            float*       dst = shg + (buf * NC + j) * SLOT;
            #pragma unroll
            for (int it = 0; it < 2; ++it) {
                int i = tid + it * NT;
                if (i < SLOT) {
                    int r   = i / FP;
                    int col = i - r * FP;
                    int gh  = min(max(h0 + r - 2, 0), H - 1);
                    int gw  = min(max(w0 + col - 4, 0), W - 1);
                    dst[i] = __ldg(fc + gh * W + gw);
                }
            }
        }
    };

    stage(0, 0);
    __syncthreads();

    for (int g = 0; g < NG; ++g) {
        if (g + 1 < NG) stage(g + 1, (g + 1) & 1);

        const float* bufp = shg + (g & 1) * NC * SLOT;
        float acc[NC];
        #pragma unroll
        for (int j = 0; j < NC; ++j) acc[j] = 0.f;
        #pragma unroll
        for (int s = 0; s < S; ++s) {
            const float* p = bufp + toff[s];
            #pragma unroll
            for (int j = 0; j < NC; ++j)
                acc[j] = fmaf(wv[s], p[j * SLOT], acc[j]);
        }
        #pragma unroll
        for (int j = 0; j < NC; ++j)
            obase[(size_t)(g * NC + j) * HW] = acc[j];

        if (do_copy) {
            // passthrough copy from smem: 1 float4 per thread per group
            int jj   = tid >> 6;          // channel within group
            int p4   = tid & 63;          // pixel-quad within tile
            int row  = p4 >> 3;
            int cg   = p4 & 7;
            float4 v = *reinterpret_cast<const float4*>(
                bufp + jj * SLOT + (row + 2) * FP + 4 + cg * 4);
            *reinterpret_cast<float4*>(
                ocbase + (size_t)(g * NC + jj) * HW + (size_t)(h0 + row) * W + w0 + cg * 4) = v;
        }
        __syncthreads();
    }
}

extern "C" void kernel_launch(void* const* d_in, const int* in_sizes, int n_in,
                              void* d_out, int out_size)
{
    const float* depth    = (const float*)d_in[0];
    const float* features = (const float*)d_in[1];
    const float* guide    = (const float*)d_in[2];
    const int*   sidx     = (const int*)d_in[3];

    float* out = (float*)d_out;
    const int featN = in_sizes[1];                       // B*C*H*W
    const int do_copy = (out_size >= 2 * featN) ? 1 : 0; // tuple output: (out, features)
    float* outf = out + featN;

    dim3 block(BW, BH);
    dim3 grid(W / BW, H / BH, 2 /*B*/);
    adaptive_sample_kernel<<<grid, block>>>(depth, features, guide, sidx,
                                            out, outf, do_copy);
}

// round 3
// speedup vs baseline: 1.5823x; 1.5823x over previous
#include <cuda_runtime.h>

// AdaptiveSample, one-shot smem staging (2 phases x 16 channels):
//   weights: softmax over 15 sampled taps of valid*posw*guide (per pixel)
//   out[b,c,h,w] = sum_s wv[s] * feat[b,c,h+dy_s,w+dx_s]  (zero-pad via masked weights)
//   second output = passthrough copy of features.

namespace {
constexpr int H  = 256;
constexpr int W  = 512;
constexpr int C  = 32;
constexpr int S  = 15;
constexpr int KS = 5;
constexpr int KK = 25;
constexpr int HW = H * W;

constexpr int BW = 32;            // tile width (warp-coalesced)
constexpr int BH = 8;             // tile height
constexpr int NT = BW * BH;       // 256 threads

constexpr int FP    = 48;         // smem pitch (floats): cols [w0-8, w0+40), float4-aligned
constexpr int FR    = 12;         // smem rows: [h0-2, h0+10)
constexpr int SLOTF = FP * FR;    // 576 floats per channel
constexpr int PC    = 16;         // channels per phase
constexpr int NP    = C / PC;     // 2 phases
constexpr int GBUF  = BH * BW * KK;  // guide tile floats (6400) — fits in feature buffer
}

__global__ __launch_bounds__(NT, 4)
void adaptive_sample_kernel(const float* __restrict__ depth,
                            const float* __restrict__ features,
                            const float* __restrict__ guide,
                            const int*   __restrict__ sidx,
                            float* __restrict__ out,
                            float* __restrict__ outf,
                            int do_copy)
{
    __shared__ float       shbuf[PC * SLOTF];   // 9216 floats = 36 KB (guide tile reuses it)
    __shared__ float       sh_posw[S];
    __shared__ int         sh_k[S];
    __shared__ signed char sh_dy[S], sh_dx[S];

    const int tx  = threadIdx.x;
    const int ty  = threadIdx.y;
    const int tid = ty * BW + tx;
    const int w0  = blockIdx.x * BW;
    const int h0  = blockIdx.y * BH;
    const int b   = blockIdx.z;

    // ---- tap metadata (one thread; S=15 trivial) ----
    if (tid == 0) {
        float pw[S];
        float sum = 0.f;
        #pragma unroll
        for (int s = 0; s < S; ++s) {
            int k  = sidx[s];
            int px = k % KS;
            int py = k / KS;
            float fx = (float)px - 2.f;
            float fy = (float)py - 2.f;
            float v  = __expf(-0.5f * sqrtf(fx * fx + fy * fy));
            pw[s] = v; sum += v;
            sh_k[s]  = k;
            sh_dy[s] = (signed char)(py - 2);
            sh_dx[s] = (signed char)(px - 2);
        }
        float inv = 1.f / sum;
        #pragma unroll
        for (int s = 0; s < S; ++s) sh_posw[s] = pw[s] * inv;
    }

    // ---- stage guide tile into shbuf (contiguous float4 rows) ----
    #pragma unroll
    for (int it = 0; it < (GBUF / 4 + NT - 1) / NT; ++it) {
        int i4 = tid + it * NT;
        if (i4 < GBUF / 4) {
            int row = i4 / (BW * KK / 4);
            int in4 = i4 - row * (BW * KK / 4);
            const float4* src = reinterpret_cast<const float4*>(
                guide + (((size_t)b * H + (h0 + row)) * W + w0) * KK) + in4;
            reinterpret_cast<float4*>(shbuf + row * BW * KK)[in4] = *src;
        }
    }
    __syncthreads();

    const int h = h0 + ty;
    const int w = w0 + tx;

    // ---- per-pixel softmax weights + smem tap offsets ----
    const float* drow = depth + (size_t)b * HW;
    const float* gpix = shbuf + (ty * BW + tx) * KK;   // lane stride 25: conflict-free

    float wv[S];
    int   toff[S];
    unsigned ibm  = 0u;
    float    gmax = 0.f;  // logits >= 0
    #pragma unroll
    for (int s = 0; s < S; ++s) {
        int dy = (int)sh_dy[s], dx = (int)sh_dx[s];
        int hh = h + dy, ww = w + dx;
        bool ib = ((unsigned)hh < (unsigned)H) && ((unsigned)ww < (unsigned)W);
        float d = ib ? __ldg(drow + hh * W + ww) : 0.f;
        bool valid = ib && (d > 0.f) && (d < 192.0f);
        float logit = valid ? sh_posw[s] * gpix[sh_k[s]] : 0.f;
        wv[s] = logit;
        gmax  = fmaxf(gmax, logit);
        ibm  |= (unsigned)ib << s;
        toff[s] = (ty + 2 + dy) * FP + (tx + 8 + dx);
    }
    float esum = 0.f;
    #pragma unroll
    for (int s = 0; s < S; ++s) { wv[s] = __expf(wv[s] - gmax); esum += wv[s]; }
    float inv = 1.f / esum;
    #pragma unroll
    for (int s = 0; s < S; ++s)
        wv[s] = ((ibm >> s) & 1u) ? wv[s] * inv : 0.f;  // OOB tap == zero-padded feature

    __syncthreads();  // guide reads done; shbuf becomes feature buffer

    const float* fbase  = features + (size_t)b * C * HW;
    const size_t pix    = (size_t)h * W + w;
    float*       obase  = out  + (size_t)b * C * HW + pix;
    float*       ocbase = outf + (size_t)b * C * HW;

    #pragma unroll
    for (int ph = 0; ph < NP; ++ph) {
        const int c0 = ph * PC;

        // ---- stage 16 channels: 12 rows x 12 float4 each, clamped (garbage only
        //      lands where tap weight is exactly 0) ----
        #pragma unroll
        for (int it = 0; it < (PC * FR * (FP / 4)) / NT; ++it) {   // 2304/256 = 9
            int i   = tid + it * NT;
            int c   = i / (FR * FP / 4);            // /144
            int rem = i - c * (FR * FP / 4);
            int r   = rem / (FP / 4);               // /12
            int q   = rem - r * (FP / 4);
            int gh  = min(max(h0 + r - 2, 0), H - 1);
            int gc  = min(max(w0 - 8 + q * 4, 0), W - 4);
            float4 v = __ldg(reinterpret_cast<const float4*>(
                fbase + (size_t)(c0 + c) * HW + gh * W + gc));
            *reinterpret_cast<float4*>(shbuf + c * SLOTF + r * FP + q * 4) = v;
        }
        __syncthreads();

        // ---- compute 16 channels from smem, 4 accumulators at a time ----
        #pragma unroll
        for (int cc = 0; cc < PC; cc += 4) {
            const float* p0 = shbuf + (cc + 0) * SLOTF;
            const float* p1 = shbuf + (cc + 1) * SLOTF;
            const float* p2 = shbuf + (cc + 2) * SLOTF;
            const float* p3 = shbuf + (cc + 3) * SLOTF;
            float a0 = 0.f, a1 = 0.f, a2 = 0.f, a3 = 0.f;
            #pragma unroll
            for (int s = 0; s < S; ++s) {
                float wt = wv[s];
                int   o  = toff[s];
                a0 = fmaf(wt, p0[o], a0);
                a1 = fmaf(wt, p1[o], a1);
                a2 = fmaf(wt, p2[o], a2);
                a3 = fmaf(wt, p3[o], a3);
            }
            obase[(size_t)(c0 + cc + 0) * HW] = a0;
            obase[(size_t)(c0 + cc + 1) * HW] = a1;
            obase[(size_t)(c0 + cc + 2) * HW] = a2;
            obase[(size_t)(c0 + cc + 3) * HW] = a3;
        }

        // ---- passthrough copy from smem: 4 float4 per thread per phase ----
        if (do_copy) {
            #pragma unroll
            for (int it = 0; it < 4; ++it) {
                int i   = tid + it * NT;      // < 1024
                int c   = i >> 6;             // channel in phase
                int rem = i & 63;
                int r   = rem >> 3;
                int q   = rem & 7;
                float4 v = *reinterpret_cast<const float4*>(
                    shbuf + c * SLOTF + (r + 2) * FP + 8 + q * 4);
                *reinterpret_cast<float4*>(
                    ocbase + (size_t)(c0 + c) * HW + (size_t)(h0 + r) * W + w0 + q * 4) = v;
            }
        }
        __syncthreads();
    }
}

extern "C" void kernel_launch(void* const* d_in, const int* in_sizes, int n_in,
                              void* d_out, int out_size)
{
    const float* depth    = (const float*)d_in[0];
    const float* features = (const float*)d_in[1];
    const float* guide    = (const float*)d_in[2];
    const int*   sidx     = (const int*)d_in[3];

    float* out = (float*)d_out;
    const int featN = in_sizes[1];                       // B*C*H*W
    const int do_copy = (out_size >= 2 * featN) ? 1 : 0; // tuple output: (out, features)
    float* outf = out + featN;

    dim3 block(BW, BH);
    dim3 grid(W / BW, H / BH, 2 /*B*/);
    adaptive_sample_kernel<<<grid, block>>>(depth, features, guide, sidx,
                                            out, outf, do_copy);
}